// round 8
// baseline (speedup 1.0000x reference)
#include <cuda_runtime.h>
#include <math.h>

#define NMAX 100000
#define EMAX 1600000
#define CDIM 40

typedef unsigned long long u64;

// ---------------------------------------------------------------------------
// Scratch (device globals — no runtime allocation allowed)
// ---------------------------------------------------------------------------
__device__ __align__(16) float g_h1[NMAX * 64];
__device__ __align__(16) float g_h2[NMAX * 64];
__device__ int g_deg[NMAX];     // in-degree per node
__device__ int g_cur[NMAX];     // fill cursors
__device__ int g_start[NMAX];   // block-local exclusive scan of deg
__device__ int g_spine[1024];   // exclusive scan of 1024-chunk totals
__device__ int g_col[EMAX];     // CSR column (src) indices grouped by dst

// ---------------------------------------------------------------------------
// f32x2 packed-FMA helpers
// ---------------------------------------------------------------------------
__device__ __forceinline__ u64 pack2(float lo, float hi) {
    u64 r;
    asm("mov.b64 %0, {%1, %2};" : "=l"(r) : "f"(lo), "f"(hi));
    return r;
}
__device__ __forceinline__ void fma2(u64& d, u64 a, u64 b) {
    asm("fma.rn.f32x2 %0, %1, %2, %0;" : "+l"(d) : "l"(a), "l"(b));
}
__device__ __forceinline__ float hsum2(u64 v) {
    float lo, hi;
    asm("mov.b64 {%0, %1}, %2;" : "=f"(lo), "=f"(hi) : "l"(v));
    return lo + hi;
}

// ---------------------------------------------------------------------------
// CSR build kernels (validated in R6)
// ---------------------------------------------------------------------------
__global__ void zero_int2_kernel(int* __restrict__ a, int* __restrict__ b, int n) {
    int i = blockIdx.x * blockDim.x + threadIdx.x;
    if (i < n) { a[i] = 0; b[i] = 0; }
}

__global__ void hist_kernel(const int* __restrict__ dst, int* __restrict__ deg, int E) {
    int e = blockIdx.x * blockDim.x + threadIdx.x;
    if (e < E) atomicAdd(&deg[dst[e]], 1);
}

__global__ void scan1_kernel(const int* __restrict__ deg, int* __restrict__ start,
                             int* __restrict__ part, int n) {
    int t = threadIdx.x;
    int gid = blockIdx.x * 1024 + t;
    int v = (gid < n) ? deg[gid] : 0;
    int lane = t & 31, w = t >> 5;
    int inc = v;
#pragma unroll
    for (int o = 1; o < 32; o <<= 1) {
        int u = __shfl_up_sync(0xffffffffu, inc, o);
        if (lane >= o) inc += u;
    }
    __shared__ int ws[32];
    if (lane == 31) ws[w] = inc;
    __syncthreads();
    if (t < 32) {
        int s = ws[t];
#pragma unroll
        for (int o = 1; o < 32; o <<= 1) {
            int u = __shfl_up_sync(0xffffffffu, s, o);
            if (t >= o) s += u;
        }
        ws[t] = s;
    }
    __syncthreads();
    int offs = (w > 0) ? ws[w - 1] : 0;
    if (gid < n) start[gid] = offs + inc - v;
    if (t == 0) part[blockIdx.x] = ws[31];
}

__global__ void spine_kernel(int* __restrict__ part, int nb) {
    int t = threadIdx.x;
    int v = (t < nb) ? part[t] : 0;
    int lane = t & 31, w = t >> 5;
    int inc = v;
#pragma unroll
    for (int o = 1; o < 32; o <<= 1) {
        int u = __shfl_up_sync(0xffffffffu, inc, o);
        if (lane >= o) inc += u;
    }
    __shared__ int ws[32];
    if (lane == 31) ws[w] = inc;
    __syncthreads();
    if (t < 32) {
        int s = ws[t];
#pragma unroll
        for (int o = 1; o < 32; o <<= 1) {
            int u = __shfl_up_sync(0xffffffffu, s, o);
            if (t >= o) s += u;
        }
        ws[t] = s;
    }
    __syncthreads();
    int offs = (w > 0) ? ws[w - 1] : 0;
    if (t < nb) part[t] = offs + inc - v;
}

__global__ void fill_kernel(const int* __restrict__ src, const int* __restrict__ dst,
                            const int* __restrict__ start, const int* __restrict__ spine,
                            int* __restrict__ cur, int* __restrict__ col, int E) {
    int e = blockIdx.x * blockDim.x + threadIdx.x;
    if (e >= E) return;
    int d = dst[e];
    int p = start[d] + spine[d >> 10] + atomicAdd(&cur[d], 1);
    col[p] = src[e];
}

// ---------------------------------------------------------------------------
// Warp-specialized fused layer.
// Block = 384 threads: 128 producer (gather-mean into 2-deep SMEM ring),
//                      256 consumer (f32x2 GEMM + bias + relu + store).
// Tile = 64 nodes. Named barriers: full{0,1}=1,2  empty{0,1}=3,4  wstage=5.
// Dynamic SMEM layout (96KB):
//   [0,16K)   sWl  u64[32][64]   (k-pair packed, zero-padded j>=OUTS)
//   [16,32K)  sWr
//   [32,48K)  sA0  float[64][64]
//   [48,64K)  sX0
//   [64,80K)  sA1
//   [80,96K)  sX1
// ---------------------------------------------------------------------------
#define BAR_SYNC(id)   asm volatile("bar.sync %0, 384;"   :: "r"(id) : "memory")
#define BAR_ARRIVE(id) asm volatile("bar.arrive %0, 384;" :: "r"(id) : "memory")

template <int OUTS, bool RELU>
__launch_bounds__(384, 2)
__global__ void layer_ws_kernel(const float4* __restrict__ xin4,
                                const int* __restrict__ start,
                                const int* __restrict__ spine,
                                const int* __restrict__ deg,
                                const int* __restrict__ col,
                                const float* __restrict__ Wl,
                                const float* __restrict__ Wr,
                                const float* __restrict__ bias,
                                float* __restrict__ out, int nN) {
    extern __shared__ __align__(16) unsigned char smem[];
    u64*   sWl = (u64*)(smem);
    u64*   sWr = (u64*)(smem + 16384);
    float* sA[2] = { (float*)(smem + 32768), (float*)(smem + 65536) };
    float* sX[2] = { (float*)(smem + 49152), (float*)(smem + 81920) };

    const int tid = threadIdx.x;
    const int nTiles = (nN + 63) >> 6;

    if (tid >= 128) {
        // ===================== CONSUMER (256 threads) =====================
        const int ctid = tid - 128;

        // Stage k-pair-packed weights (zero-pad rows j >= OUTS)
        for (int idx = ctid; idx < 2048; idx += 256) {
            int kp = idx >> 6;
            int j  = idx & 63;
            float l0 = 0.f, l1 = 0.f, r0 = 0.f, r1 = 0.f;
            if (j < OUTS) {
                l0 = Wl[j * 64 + 2 * kp]; l1 = Wl[j * 64 + 2 * kp + 1];
                r0 = Wr[j * 64 + 2 * kp]; r1 = Wr[j * 64 + 2 * kp + 1];
            }
            sWl[idx] = pack2(l0, l1);
            sWr[idx] = pack2(r0, r1);
        }
        asm volatile("bar.sync 5, 256;" ::: "memory");

        const int j = ctid & 63;          // output column
        const int g = ctid >> 6;          // node group (16 nodes)
        const float bj = (j < OUTS) ? __ldg(&bias[j]) : 0.f;

        int c = 0;
        for (int t = blockIdx.x; t < nTiles; t += gridDim.x, c++) {
            const int b = c & 1;
            BAR_SYNC(1 + b);              // wait buffer full

            const u64* rA = (const u64*)sA[b] + (g * 16) * 32;
            const u64* rX = (const u64*)sX[b] + (g * 16) * 32;

            u64 acc[16];
#pragma unroll
            for (int n = 0; n < 16; n++) acc[n] = 0ull;

#pragma unroll 4
            for (int kp = 0; kp < 32; kp++) {
                u64 wl = sWl[kp * 64 + j];
                u64 wr = sWr[kp * 64 + j];
#pragma unroll
                for (int n = 0; n < 16; n++) {
                    fma2(acc[n], rA[n * 32 + kp], wl);
                    fma2(acc[n], rX[n * 32 + kp], wr);
                }
            }

            BAR_ARRIVE(3 + b);            // buffer free for producer

            const int base = (t << 6) + g * 16;
#pragma unroll
            for (int n = 0; n < 16; n++) {
                float r = hsum2(acc[n]) + bj;
                if (RELU) r = fmaxf(r, 0.f);
                int node = base + n;
                if (node < nN && j < OUTS) out[node * OUTS + j] = r;
            }
        }
    } else {
        // ===================== PRODUCER (128 threads) =====================
        const int gn = tid >> 2;          // node within 32-node half-pass
        const int q  = tid & 3;           // chunk lane: chunks q, q+4, q+8, q+12

        int c = 0;
        for (int t = blockIdx.x; t < nTiles; t += gridDim.x, c++) {
            const int b = c & 1;
            if (c >= 2) BAR_SYNC(3 + b);  // wait buffer free

            float* bA = sA[b];
            float* bX = sX[b];

#pragma unroll
            for (int half = 0; half < 2; half++) {
                const int ln   = half * 32 + gn;   // node within tile
                const int node = (t << 6) + ln;

                float4 a0 = {0,0,0,0}, a1 = {0,0,0,0}, a2 = {0,0,0,0}, a3 = {0,0,0,0};
                float4 x0 = {0,0,0,0}, x1 = {0,0,0,0}, x2 = {0,0,0,0}, x3 = {0,0,0,0};

                if (node < nN) {
                    const int d = __ldg(&deg[node]);
                    const int p = __ldg(&start[node]) + __ldg(&spine[node >> 10]);
                    int i = 0;
                    for (; i + 2 <= d; i += 2) {
                        int n0 = __ldg(&col[p + i]);
                        int n1 = __ldg(&col[p + i + 1]);
                        const float4* r0 = xin4 + n0 * 16 + q;
                        const float4* r1 = xin4 + n1 * 16 + q;
                        float4 v00 = __ldg(r0 + 0), v01 = __ldg(r0 + 4);
                        float4 v02 = __ldg(r0 + 8), v03 = __ldg(r0 + 12);
                        float4 v10 = __ldg(r1 + 0), v11 = __ldg(r1 + 4);
                        float4 v12 = __ldg(r1 + 8), v13 = __ldg(r1 + 12);
                        a0.x += v00.x + v10.x; a0.y += v00.y + v10.y;
                        a0.z += v00.z + v10.z; a0.w += v00.w + v10.w;
                        a1.x += v01.x + v11.x; a1.y += v01.y + v11.y;
                        a1.z += v01.z + v11.z; a1.w += v01.w + v11.w;
                        a2.x += v02.x + v12.x; a2.y += v02.y + v12.y;
                        a2.z += v02.z + v12.z; a2.w += v02.w + v12.w;
                        a3.x += v03.x + v13.x; a3.y += v03.y + v13.y;
                        a3.z += v03.z + v13.z; a3.w += v03.w + v13.w;
                    }
                    if (i < d) {
                        int n0 = __ldg(&col[p + i]);
                        const float4* r0 = xin4 + n0 * 16 + q;
                        float4 v00 = __ldg(r0 + 0), v01 = __ldg(r0 + 4);
                        float4 v02 = __ldg(r0 + 8), v03 = __ldg(r0 + 12);
                        a0.x += v00.x; a0.y += v00.y; a0.z += v00.z; a0.w += v00.w;
                        a1.x += v01.x; a1.y += v01.y; a1.z += v01.z; a1.w += v01.w;
                        a2.x += v02.x; a2.y += v02.y; a2.z += v02.z; a2.w += v02.w;
                        a3.x += v03.x; a3.y += v03.y; a3.z += v03.z; a3.w += v03.w;
                    }
                    const float iv = 1.0f / fmaxf((float)d, 1.0f);
                    a0.x *= iv; a0.y *= iv; a0.z *= iv; a0.w *= iv;
                    a1.x *= iv; a1.y *= iv; a1.z *= iv; a1.w *= iv;
                    a2.x *= iv; a2.y *= iv; a2.z *= iv; a2.w *= iv;
                    a3.x *= iv; a3.y *= iv; a3.z *= iv; a3.w *= iv;

                    const float4* rs = xin4 + node * 16 + q;
                    x0 = __ldg(rs + 0); x1 = __ldg(rs + 4);
                    x2 = __ldg(rs + 8); x3 = __ldg(rs + 12);
                }

                float4* dA = (float4*)bA + ln * 16;
                float4* dX = (float4*)bX + ln * 16;
                dA[q] = a0; dA[q + 4] = a1; dA[q + 8] = a2; dA[q + 12] = a3;
                dX[q] = x0; dX[q + 4] = x1; dX[q + 8] = x2; dX[q + 12] = x3;
            }

            __threadfence_block();
            BAR_ARRIVE(1 + b);            // buffer full for consumer
        }
    }
}

// ---------------------------------------------------------------------------
// In-place log_softmax over rows of 40 (one warp per row)
// ---------------------------------------------------------------------------
__global__ void lsm_kernel(float* __restrict__ out, int n) {
    int w    = (blockIdx.x * blockDim.x + threadIdx.x) >> 5;
    int lane = threadIdx.x & 31;
    if (w >= n) return;
    float* row = out + (size_t)w * CDIM;

    float v0 = (lane < CDIM)      ? row[lane]      : -3.4e38f;
    float v1 = (lane + 32 < CDIM) ? row[lane + 32] : -3.4e38f;

    float m = fmaxf(v0, v1);
#pragma unroll
    for (int o = 16; o; o >>= 1) m = fmaxf(m, __shfl_xor_sync(0xffffffffu, m, o));

    float s = ((lane < CDIM) ? expf(v0 - m) : 0.f) +
              ((lane + 32 < CDIM) ? expf(v1 - m) : 0.f);
#pragma unroll
    for (int o = 16; o; o >>= 1) s += __shfl_xor_sync(0xffffffffu, s, o);

    float l = m + logf(s);
    if (lane < CDIM)      row[lane]      = v0 - l;
    if (lane + 32 < CDIM) row[lane + 32] = v1 - l;
}

// ---------------------------------------------------------------------------
// kernel_launch
// ---------------------------------------------------------------------------
extern "C" void kernel_launch(void* const* d_in, const int* in_sizes, int n_in,
                              void* d_out, int out_size) {
    const float* x   = (const float*)d_in[0];
    const int*   ei  = (const int*)d_in[1];
    const float* Wl1 = (const float*)d_in[2];
    const float* Wr1 = (const float*)d_in[3];
    const float* b1  = (const float*)d_in[4];
    const float* Wl2 = (const float*)d_in[5];
    const float* Wr2 = (const float*)d_in[6];
    const float* b2  = (const float*)d_in[7];
    const float* Wl3 = (const float*)d_in[8];
    const float* Wr3 = (const float*)d_in[9];
    const float* b3  = (const float*)d_in[10];
    float* out = (float*)d_out;

    const int N = in_sizes[0] / 64;
    const int E = in_sizes[1] / 2;
    const int* src = ei;
    const int* dst = ei + E;

    int *deg, *cur, *start, *spine, *col;
    float *h1, *h2;
    cudaGetSymbolAddress((void**)&deg,   g_deg);
    cudaGetSymbolAddress((void**)&cur,   g_cur);
    cudaGetSymbolAddress((void**)&start, g_start);
    cudaGetSymbolAddress((void**)&spine, g_spine);
    cudaGetSymbolAddress((void**)&col,   g_col);
    cudaGetSymbolAddress((void**)&h1,    g_h1);
    cudaGetSymbolAddress((void**)&h2,    g_h2);

    const int SMEM = 96 * 1024;
    cudaFuncSetAttribute(layer_ws_kernel<64, true>,
                         cudaFuncAttributeMaxDynamicSharedMemorySize, SMEM);
    cudaFuncSetAttribute(layer_ws_kernel<40, false>,
                         cudaFuncAttributeMaxDynamicSharedMemorySize, SMEM);

    const int nScanB = (N + 1023) / 1024;
    const int edgeB  = (E + 255) / 256;
    const int layerB = 296;   // 2 blocks/SM * 148 SMs

    // CSR build
    zero_int2_kernel<<<(N + 255) / 256, 256>>>(deg, cur, N);
    hist_kernel<<<edgeB, 256>>>(dst, deg, E);
    scan1_kernel<<<nScanB, 1024>>>(deg, start, spine, N);
    spine_kernel<<<1, 1024>>>(spine, nScanB);
    fill_kernel<<<edgeB, 256>>>(src, dst, start, spine, cur, col, E);

    // Warp-specialized fused layers
    layer_ws_kernel<64, true ><<<layerB, 384, SMEM>>>((const float4*)x,  start, spine, deg, col, Wl1, Wr1, b1, h1,  N);
    layer_ws_kernel<64, true ><<<layerB, 384, SMEM>>>((const float4*)h1, start, spine, deg, col, Wl2, Wr2, b2, h2,  N);
    layer_ws_kernel<40, false><<<layerB, 384, SMEM>>>((const float4*)h2, start, spine, deg, col, Wl3, Wr3, b3, out, N);

    lsm_kernel<<<(N * 32 + 255) / 256, 256>>>(out, N);
}

// round 9
// speedup vs baseline: 1.3209x; 1.3209x over previous
#include <cuda_runtime.h>
#include <math.h>

#define NMAX 100000
#define EMAX 1600000
#define CDIM 40
#define SCAP 1280   // SMEM col-stage capacity per 32-node tile (avg 512 edges)

typedef unsigned long long u64;

// ---------------------------------------------------------------------------
// Scratch (device globals — no runtime allocation allowed)
// ---------------------------------------------------------------------------
__device__ __align__(16) float g_h1[NMAX * 64];
__device__ __align__(16) float g_h2[NMAX * 64];
__device__ int g_deg[NMAX];     // in-degree per node
__device__ int g_cur[NMAX];     // fill cursors
__device__ int g_start[NMAX];   // 1024-chunk-local exclusive scan of deg
__device__ int g_spine[1024];   // exclusive scan of chunk totals
__device__ int g_col[EMAX];     // CSR column (src) indices grouped by dst

// ---------------------------------------------------------------------------
// f32x2 packed-FMA helpers
// ---------------------------------------------------------------------------
__device__ __forceinline__ u64 pack2(float lo, float hi) {
    u64 r;
    asm("mov.b64 %0, {%1, %2};" : "=l"(r) : "f"(lo), "f"(hi));
    return r;
}
__device__ __forceinline__ void fma2(u64& d, u64 a, u64 b) {
    asm("fma.rn.f32x2 %0, %1, %2, %0;" : "+l"(d) : "l"(a), "l"(b));
}
__device__ __forceinline__ float hsum2(u64 v) {
    float lo, hi;
    asm("mov.b64 {%0, %1}, %2;" : "=f"(lo), "=f"(hi) : "l"(v));
    return lo + hi;
}

// ---------------------------------------------------------------------------
// CSR build kernels (validated R6/R7)
// ---------------------------------------------------------------------------
__global__ void zero_int2_kernel(int* __restrict__ a, int* __restrict__ b, int n) {
    int i = blockIdx.x * blockDim.x + threadIdx.x;
    if (i < n) { a[i] = 0; b[i] = 0; }
}

__global__ void hist_kernel(const int* __restrict__ dst, int* __restrict__ deg, int E) {
    int e = blockIdx.x * blockDim.x + threadIdx.x;
    if (e < E) atomicAdd(&deg[dst[e]], 1);
}

__global__ void scan1_kernel(const int* __restrict__ deg, int* __restrict__ start,
                             int* __restrict__ part, int n) {
    int t = threadIdx.x;
    int gid = blockIdx.x * 1024 + t;
    int v = (gid < n) ? deg[gid] : 0;
    int lane = t & 31, w = t >> 5;
    int inc = v;
#pragma unroll
    for (int o = 1; o < 32; o <<= 1) {
        int u = __shfl_up_sync(0xffffffffu, inc, o);
        if (lane >= o) inc += u;
    }
    __shared__ int ws[32];
    if (lane == 31) ws[w] = inc;
    __syncthreads();
    if (t < 32) {
        int s = ws[t];
#pragma unroll
        for (int o = 1; o < 32; o <<= 1) {
            int u = __shfl_up_sync(0xffffffffu, s, o);
            if (t >= o) s += u;
        }
        ws[t] = s;
    }
    __syncthreads();
    int offs = (w > 0) ? ws[w - 1] : 0;
    if (gid < n) start[gid] = offs + inc - v;
    if (t == 0) part[blockIdx.x] = ws[31];
}

__global__ void spine_kernel(int* __restrict__ part, int nb) {
    int t = threadIdx.x;
    int v = (t < nb) ? part[t] : 0;
    int lane = t & 31, w = t >> 5;
    int inc = v;
#pragma unroll
    for (int o = 1; o < 32; o <<= 1) {
        int u = __shfl_up_sync(0xffffffffu, inc, o);
        if (lane >= o) inc += u;
    }
    __shared__ int ws[32];
    if (lane == 31) ws[w] = inc;
    __syncthreads();
    if (t < 32) {
        int s = ws[t];
#pragma unroll
        for (int o = 1; o < 32; o <<= 1) {
            int u = __shfl_up_sync(0xffffffffu, s, o);
            if (t >= o) s += u;
        }
        ws[t] = s;
    }
    __syncthreads();
    int offs = (w > 0) ? ws[w - 1] : 0;
    if (t < nb) part[t] = offs + inc - v;
}

__global__ void fill_kernel(const int* __restrict__ src, const int* __restrict__ dst,
                            const int* __restrict__ start, const int* __restrict__ spine,
                            int* __restrict__ cur, int* __restrict__ col, int E) {
    int e = blockIdx.x * blockDim.x + threadIdx.x;
    if (e >= E) return;
    int d = dst[e];
    int p = start[d] + spine[d >> 10] + atomicAdd(&cur[d], 1);
    col[p] = src[e];
}

// ---------------------------------------------------------------------------
// Fused layer (phased, R6 structure + SMEM col staging + unroll-4 gather).
// 256 threads, tile = 32 nodes.
// Dynamic SMEM (53.25KB):
//   [0,16K)      sWl  u64[32][64] k-pair packed (zero-pad j>=OUTS)
//   [16K,32K)    sWr
//   [32K,40K)    sA   float[32][64]
//   [40K,48K)    sX
//   [48K,53.25K) scol int[SCAP]
// ---------------------------------------------------------------------------
template <int OUTS, bool RELU>
__launch_bounds__(256)
__global__ void layer_kernel(const float4* __restrict__ xin4,
                             const int* __restrict__ start,
                             const int* __restrict__ spine,
                             const int* __restrict__ deg,
                             const int* __restrict__ col,
                             const float* __restrict__ Wl,
                             const float* __restrict__ Wr,
                             const float* __restrict__ bias,
                             float* __restrict__ out, int nN) {
    extern __shared__ __align__(16) unsigned char smem[];
    u64*   sWl  = (u64*)(smem);
    u64*   sWr  = (u64*)(smem + 16384);
    float* sA   = (float*)(smem + 32768);
    float* sX   = (float*)(smem + 40960);
    int*   scol = (int*)(smem + 49152);

    const int tid = threadIdx.x;

    // Stage k-pair-packed weights once (zero-pad rows j >= OUTS)
    for (int idx = tid; idx < 2048; idx += 256) {
        int kp = idx >> 6;
        int j  = idx & 63;
        float l0 = 0.f, l1 = 0.f, r0 = 0.f, r1 = 0.f;
        if (j < OUTS) {
            l0 = Wl[j * 64 + 2 * kp]; l1 = Wl[j * 64 + 2 * kp + 1];
            r0 = Wr[j * 64 + 2 * kp]; r1 = Wr[j * 64 + 2 * kp + 1];
        }
        sWl[idx] = pack2(l0, l1);
        sWr[idx] = pack2(r0, r1);
    }

    const int j  = tid & 31;   // GEMM: output column (and j+32)
    const int g  = tid >> 5;   // GEMM: node group (4 nodes)
    const int gn = tid >> 3;   // gather: node within tile
    const int q  = tid & 7;    // gather: float4 chunk (q and q+8)
    const float bj0 = (j < OUTS) ? __ldg(&bias[j]) : 0.f;
    const float bj1 = (j + 32 < OUTS) ? __ldg(&bias[j + 32]) : 0.f;

    const int nTiles = (nN + 31) >> 5;
    for (int t = blockIdx.x; t < nTiles; t += gridDim.x) {
        __syncthreads();   // SMEM reuse guard (covers weight stage on first iter)
        const int base = t << 5;

        // ---- Stage this tile's CSR col indices into SMEM (coalesced) ----
        // Tiles are 32-aligned, chunks are 1024 nodes => tile never crosses a
        // chunk, so 'start' values within the tile share one spine offset and
        // the tile's edges are contiguous: [P0, P0 + tE).
        const int s0    = __ldg(&start[base]);
        const int lastN = min(base + 31, nN - 1);
        const int tE    = __ldg(&start[lastN]) + __ldg(&deg[lastN]) - s0;
        const int P0    = s0 + __ldg(&spine[base >> 10]);
        const int nStage = (tE < SCAP) ? tE : SCAP;
        for (int i2 = tid; i2 < nStage; i2 += 256) scol[i2] = __ldg(&col[P0 + i2]);
        __syncthreads();

        // ---- Gather-mean into sA, self rows into sX ----
        const int node = base + gn;
        float4 a0 = {0,0,0,0}, a1 = {0,0,0,0};
        float4 x0 = {0,0,0,0}, x1 = {0,0,0,0};
        if (node < nN) {
            const int d  = __ldg(&deg[node]);
            const int pl = __ldg(&start[node]) - s0;   // tile-local edge offset

            const float4* rs = xin4 + (size_t)node * 16 + q;
            x0 = __ldg(rs);
            x1 = __ldg(rs + 8);

            int i = 0;
            for (; i + 4 <= d; i += 4) {
                const int e0 = pl + i;
                int n0 = (e0 + 0 < SCAP) ? scol[e0 + 0] : __ldg(&col[P0 + e0 + 0]);
                int n1 = (e0 + 1 < SCAP) ? scol[e0 + 1] : __ldg(&col[P0 + e0 + 1]);
                int n2 = (e0 + 2 < SCAP) ? scol[e0 + 2] : __ldg(&col[P0 + e0 + 2]);
                int n3 = (e0 + 3 < SCAP) ? scol[e0 + 3] : __ldg(&col[P0 + e0 + 3]);
                const float4* r0 = xin4 + (size_t)n0 * 16 + q;
                const float4* r1 = xin4 + (size_t)n1 * 16 + q;
                const float4* r2 = xin4 + (size_t)n2 * 16 + q;
                const float4* r3 = xin4 + (size_t)n3 * 16 + q;
                float4 v0a = __ldg(r0), v0b = __ldg(r0 + 8);
                float4 v1a = __ldg(r1), v1b = __ldg(r1 + 8);
                float4 v2a = __ldg(r2), v2b = __ldg(r2 + 8);
                float4 v3a = __ldg(r3), v3b = __ldg(r3 + 8);
                a0.x += (v0a.x + v1a.x) + (v2a.x + v3a.x);
                a0.y += (v0a.y + v1a.y) + (v2a.y + v3a.y);
                a0.z += (v0a.z + v1a.z) + (v2a.z + v3a.z);
                a0.w += (v0a.w + v1a.w) + (v2a.w + v3a.w);
                a1.x += (v0b.x + v1b.x) + (v2b.x + v3b.x);
                a1.y += (v0b.y + v1b.y) + (v2b.y + v3b.y);
                a1.z += (v0b.z + v1b.z) + (v2b.z + v3b.z);
                a1.w += (v0b.w + v1b.w) + (v2b.w + v3b.w);
            }
            for (; i < d; i++) {
                const int e0 = pl + i;
                int n0 = (e0 < SCAP) ? scol[e0] : __ldg(&col[P0 + e0]);
                const float4* r0 = xin4 + (size_t)n0 * 16 + q;
                float4 v0a = __ldg(r0), v0b = __ldg(r0 + 8);
                a0.x += v0a.x; a0.y += v0a.y; a0.z += v0a.z; a0.w += v0a.w;
                a1.x += v0b.x; a1.y += v0b.y; a1.z += v0b.z; a1.w += v0b.w;
            }
            const float iv = 1.0f / fmaxf((float)d, 1.0f);
            a0.x *= iv; a0.y *= iv; a0.z *= iv; a0.w *= iv;
            a1.x *= iv; a1.y *= iv; a1.z *= iv; a1.w *= iv;
        }
        ((float4*)sA)[gn * 16 + q]     = a0;
        ((float4*)sA)[gn * 16 + q + 8] = a1;
        ((float4*)sX)[gn * 16 + q]     = x0;
        ((float4*)sX)[gn * 16 + q + 8] = x1;
        __syncthreads();

        // ---- GEMM: thread = (j, j+32) x 4 nodes (fma-pipe-bound, R6) ----
        u64 acc00 = 0, acc01 = 0, acc02 = 0, acc03 = 0;
        u64 acc10 = 0, acc11 = 0, acc12 = 0, acc13 = 0;
        const u64* pA = (const u64*)sA + (g * 4) * 32;
        const u64* pX = (const u64*)sX + (g * 4) * 32;

#pragma unroll 8
        for (int kp = 0; kp < 32; kp++) {
            u64 wl0 = sWl[kp * 64 + j];
            u64 wl1 = sWl[kp * 64 + j + 32];
            u64 wr0 = sWr[kp * 64 + j];
            u64 wr1 = sWr[kp * 64 + j + 32];
            u64 av0 = pA[kp], av1 = pA[32 + kp], av2 = pA[64 + kp], av3 = pA[96 + kp];
            u64 xv0 = pX[kp], xv1 = pX[32 + kp], xv2 = pX[64 + kp], xv3 = pX[96 + kp];
            fma2(acc00, av0, wl0); fma2(acc00, xv0, wr0);
            fma2(acc01, av1, wl0); fma2(acc01, xv1, wr0);
            fma2(acc02, av2, wl0); fma2(acc02, xv2, wr0);
            fma2(acc03, av3, wl0); fma2(acc03, xv3, wr0);
            fma2(acc10, av0, wl1); fma2(acc10, xv0, wr1);
            fma2(acc11, av1, wl1); fma2(acc11, xv1, wr1);
            fma2(acc12, av2, wl1); fma2(acc12, xv2, wr1);
            fma2(acc13, av3, wl1); fma2(acc13, xv3, wr1);
        }

        float r00 = hsum2(acc00) + bj0, r01 = hsum2(acc01) + bj0;
        float r02 = hsum2(acc02) + bj0, r03 = hsum2(acc03) + bj0;
        float r10 = hsum2(acc10) + bj1, r11 = hsum2(acc11) + bj1;
        float r12 = hsum2(acc12) + bj1, r13 = hsum2(acc13) + bj1;
        if (RELU) {
            r00 = fmaxf(r00, 0.f); r01 = fmaxf(r01, 0.f);
            r02 = fmaxf(r02, 0.f); r03 = fmaxf(r03, 0.f);
            r10 = fmaxf(r10, 0.f); r11 = fmaxf(r11, 0.f);
            r12 = fmaxf(r12, 0.f); r13 = fmaxf(r13, 0.f);
        }
        const int n0 = base + g * 4;
        const bool hi = (j + 32 < OUTS);
        if (n0 + 0 < nN) { out[(n0 + 0) * OUTS + j] = r00; if (hi) out[(n0 + 0) * OUTS + j + 32] = r10; }
        if (n0 + 1 < nN) { out[(n0 + 1) * OUTS + j] = r01; if (hi) out[(n0 + 1) * OUTS + j + 32] = r11; }
        if (n0 + 2 < nN) { out[(n0 + 2) * OUTS + j] = r02; if (hi) out[(n0 + 2) * OUTS + j + 32] = r12; }
        if (n0 + 3 < nN) { out[(n0 + 3) * OUTS + j] = r03; if (hi) out[(n0 + 3) * OUTS + j + 32] = r13; }
    }
}

// ---------------------------------------------------------------------------
// In-place log_softmax over rows of 40 (one warp per row)
// ---------------------------------------------------------------------------
__global__ void lsm_kernel(float* __restrict__ out, int n) {
    int w    = (blockIdx.x * blockDim.x + threadIdx.x) >> 5;
    int lane = threadIdx.x & 31;
    if (w >= n) return;
    float* row = out + (size_t)w * CDIM;

    float v0 = (lane < CDIM)      ? row[lane]      : -3.4e38f;
    float v1 = (lane + 32 < CDIM) ? row[lane + 32] : -3.4e38f;

    float m = fmaxf(v0, v1);
#pragma unroll
    for (int o = 16; o; o >>= 1) m = fmaxf(m, __shfl_xor_sync(0xffffffffu, m, o));

    float s = ((lane < CDIM) ? expf(v0 - m) : 0.f) +
              ((lane + 32 < CDIM) ? expf(v1 - m) : 0.f);
#pragma unroll
    for (int o = 16; o; o >>= 1) s += __shfl_xor_sync(0xffffffffu, s, o);

    float l = m + logf(s);
    if (lane < CDIM)      row[lane]      = v0 - l;
    if (lane + 32 < CDIM) row[lane + 32] = v1 - l;
}

// ---------------------------------------------------------------------------
// kernel_launch
// ---------------------------------------------------------------------------
extern "C" void kernel_launch(void* const* d_in, const int* in_sizes, int n_in,
                              void* d_out, int out_size) {
    const float* x   = (const float*)d_in[0];
    const int*   ei  = (const int*)d_in[1];
    const float* Wl1 = (const float*)d_in[2];
    const float* Wr1 = (const float*)d_in[3];
    const float* b1  = (const float*)d_in[4];
    const float* Wl2 = (const float*)d_in[5];
    const float* Wr2 = (const float*)d_in[6];
    const float* b2  = (const float*)d_in[7];
    const float* Wl3 = (const float*)d_in[8];
    const float* Wr3 = (const float*)d_in[9];
    const float* b3  = (const float*)d_in[10];
    float* out = (float*)d_out;

    const int N = in_sizes[0] / 64;
    const int E = in_sizes[1] / 2;
    const int* src = ei;
    const int* dst = ei + E;

    int *deg, *cur, *start, *spine, *col;
    float *h1, *h2;
    cudaGetSymbolAddress((void**)&deg,   g_deg);
    cudaGetSymbolAddress((void**)&cur,   g_cur);
    cudaGetSymbolAddress((void**)&start, g_start);
    cudaGetSymbolAddress((void**)&spine, g_spine);
    cudaGetSymbolAddress((void**)&col,   g_col);
    cudaGetSymbolAddress((void**)&h1,    g_h1);
    cudaGetSymbolAddress((void**)&h2,    g_h2);

    const int SMEM = 49152 + SCAP * 4;   // 53.25 KB dynamic
    cudaFuncSetAttribute(layer_kernel<64, true>,
                         cudaFuncAttributeMaxDynamicSharedMemorySize, SMEM);
    cudaFuncSetAttribute(layer_kernel<40, false>,
                         cudaFuncAttributeMaxDynamicSharedMemorySize, SMEM);

    const int nScanB = (N + 1023) / 1024;
    const int edgeB  = (E + 255) / 256;
    const int layerB = 592;   // grid-stride over 3125 tiles

    // CSR build
    zero_int2_kernel<<<(N + 255) / 256, 256>>>(deg, cur, N);
    hist_kernel<<<edgeB, 256>>>(dst, deg, E);
    scan1_kernel<<<nScanB, 1024>>>(deg, start, spine, N);
    spine_kernel<<<1, 1024>>>(spine, nScanB);
    fill_kernel<<<edgeB, 256>>>(src, dst, start, spine, cur, col, E);

    // Fused layers
    layer_kernel<64, true ><<<layerB, 256, SMEM>>>((const float4*)x,  start, spine, deg, col, Wl1, Wr1, b1, h1,  N);
    layer_kernel<64, true ><<<layerB, 256, SMEM>>>((const float4*)h1, start, spine, deg, col, Wl2, Wr2, b2, h2,  N);
    layer_kernel<40, false><<<layerB, 256, SMEM>>>((const float4*)h2, start, spine, deg, col, Wl3, Wr3, b3, out, N);

    lsm_kernel<<<(N * 32 + 255) / 256, 256>>>(out, N);
}